// round 1
// baseline (speedup 1.0000x reference)
#include <cuda_runtime.h>
#include <cuda_bf16.h>

// Problem constants (fixed shapes per reference)
#define BATCH 4
#define SEQ   2048
#define DMODEL 1024
#define DPROJ  256

// GEMM tiling
#define BM 128
#define BN 128
#define BK 16
#define TM 8
#define TN 8
#define NTHREADS 256   // 16 x 16 threads, each owns an 8x8 micro-tile

// Scratch for h = relu(hs @ W^T + b): [4*2048, 256] f32 = 8 MB
__device__ float g_h[BATCH * SEQ * DPROJ];

// ---------------------------------------------------------------------------
// GEMM1: h = relu(A @ W^T + bias)
//   A  = hidden_states viewed as [M=8192, K=1024] (row-major, K contiguous)
//   W  = proj_w [N=256, K=1024]                   (row-major, K contiguous)
//   out= g_h [M, 256]
// Both operands are K-contiguous -> identical tile-load code for A and B.
// ---------------------------------------------------------------------------
__global__ __launch_bounds__(NTHREADS)
void proj_relu_kernel(const float* __restrict__ A,
                      const float* __restrict__ W,
                      const float* __restrict__ bias)
{
    const int K = DMODEL;
    const int tid = threadIdx.x;
    const int tx = tid & 15;
    const int ty = tid >> 4;

    const float* Ablk = A + (size_t)blockIdx.x * BM * K;
    const float* Bblk = W + (size_t)blockIdx.y * BN * K;

    __shared__ float As[BK][BM];
    __shared__ float Bs[BK][BN];

    float acc[TM][TN];
#pragma unroll
    for (int i = 0; i < TM; i++)
#pragma unroll
        for (int j = 0; j < TN; j++) acc[i][j] = 0.0f;

    for (int k0 = 0; k0 < K; k0 += BK) {
        // Load 128x16 tiles for A and B. 512 float4 chunks each, 2 per thread.
#pragma unroll
        for (int q = 0; q < 2; q++) {
            int c   = tid + q * NTHREADS;   // 0..511
            int row = c >> 2;               // 0..127
            int kc  = (c & 3) << 2;         // 0,4,8,12
            float4 va = *reinterpret_cast<const float4*>(Ablk + (size_t)row * K + k0 + kc);
            As[kc + 0][row] = va.x; As[kc + 1][row] = va.y;
            As[kc + 2][row] = va.z; As[kc + 3][row] = va.w;
            float4 vb = *reinterpret_cast<const float4*>(Bblk + (size_t)row * K + k0 + kc);
            Bs[kc + 0][row] = vb.x; Bs[kc + 1][row] = vb.y;
            Bs[kc + 2][row] = vb.z; Bs[kc + 3][row] = vb.w;
        }
        __syncthreads();

#pragma unroll
        for (int k = 0; k < BK; k++) {
            float a[TM], b[TN];
            *reinterpret_cast<float4*>(&a[0]) = *reinterpret_cast<const float4*>(&As[k][ty * TM]);
            *reinterpret_cast<float4*>(&a[4]) = *reinterpret_cast<const float4*>(&As[k][ty * TM + 4]);
            *reinterpret_cast<float4*>(&b[0]) = *reinterpret_cast<const float4*>(&Bs[k][tx * TN]);
            *reinterpret_cast<float4*>(&b[4]) = *reinterpret_cast<const float4*>(&Bs[k][tx * TN + 4]);
#pragma unroll
            for (int i = 0; i < TM; i++)
#pragma unroll
                for (int j = 0; j < TN; j++)
                    acc[i][j] = fmaf(a[i], b[j], acc[i][j]);
        }
        __syncthreads();
    }

    // Epilogue: +bias, relu, store to g_h
    const int row0 = blockIdx.x * BM + ty * TM;
    const int col0 = blockIdx.y * BN + tx * TN;
    float bj[TN];
#pragma unroll
    for (int j = 0; j < TN; j++) bj[j] = bias[col0 + j];
#pragma unroll
    for (int i = 0; i < TM; i++) {
        float4 r0, r1;
        r0.x = fmaxf(acc[i][0] + bj[0], 0.0f);
        r0.y = fmaxf(acc[i][1] + bj[1], 0.0f);
        r0.z = fmaxf(acc[i][2] + bj[2], 0.0f);
        r0.w = fmaxf(acc[i][3] + bj[3], 0.0f);
        r1.x = fmaxf(acc[i][4] + bj[4], 0.0f);
        r1.y = fmaxf(acc[i][5] + bj[5], 0.0f);
        r1.z = fmaxf(acc[i][6] + bj[6], 0.0f);
        r1.w = fmaxf(acc[i][7] + bj[7], 0.0f);
        *reinterpret_cast<float4*>(&g_h[(size_t)(row0 + i) * DPROJ + col0])     = r0;
        *reinterpret_cast<float4*>(&g_h[(size_t)(row0 + i) * DPROJ + col0 + 4]) = r1;
    }
}

// ---------------------------------------------------------------------------
// GEMM2: scores[b] = (h_b @ h_b^T) * clf_w + clf_b
// Symmetric: only upper-triangular 128x128 tiles (bj >= bi) are computed;
// off-diagonal tiles also store the mirrored transpose. 16x16 tile grid
// -> 136 tile-blocks per batch.
// ---------------------------------------------------------------------------
__global__ __launch_bounds__(NTHREADS)
void score_kernel(const float* __restrict__ clf_w,
                  const float* __restrict__ clf_b,
                  float* __restrict__ out)
{
    const int K = DPROJ;        // 256
    const int b = blockIdx.y;

    // Decode linear tile index -> (bi, bj) with bi <= bj, 16x16 tile grid
    int t = blockIdx.x;
    int bi = 0;
    int rem = SEQ / BM;         // 16
    while (t >= rem) { t -= rem; bi++; rem--; }
    const int bj = bi + t;

    const float* Hb  = g_h + (size_t)b * SEQ * DPROJ;
    const float* Ablk = Hb + (size_t)bi * BM * K;
    const float* Bblk = Hb + (size_t)bj * BN * K;

    const int tid = threadIdx.x;
    const int tx = tid & 15;
    const int ty = tid >> 4;

    __shared__ float As[BK][BM];
    __shared__ float Bs[BK][BN];

    float acc[TM][TN];
#pragma unroll
    for (int i = 0; i < TM; i++)
#pragma unroll
        for (int j = 0; j < TN; j++) acc[i][j] = 0.0f;

    for (int k0 = 0; k0 < K; k0 += BK) {
#pragma unroll
        for (int q = 0; q < 2; q++) {
            int c   = tid + q * NTHREADS;
            int row = c >> 2;
            int kc  = (c & 3) << 2;
            float4 va = *reinterpret_cast<const float4*>(Ablk + (size_t)row * K + k0 + kc);
            As[kc + 0][row] = va.x; As[kc + 1][row] = va.y;
            As[kc + 2][row] = va.z; As[kc + 3][row] = va.w;
            float4 vb = *reinterpret_cast<const float4*>(Bblk + (size_t)row * K + k0 + kc);
            Bs[kc + 0][row] = vb.x; Bs[kc + 1][row] = vb.y;
            Bs[kc + 2][row] = vb.z; Bs[kc + 3][row] = vb.w;
        }
        __syncthreads();

#pragma unroll
        for (int k = 0; k < BK; k++) {
            float a[TM], bb[TN];
            *reinterpret_cast<float4*>(&a[0])  = *reinterpret_cast<const float4*>(&As[k][ty * TM]);
            *reinterpret_cast<float4*>(&a[4])  = *reinterpret_cast<const float4*>(&As[k][ty * TM + 4]);
            *reinterpret_cast<float4*>(&bb[0]) = *reinterpret_cast<const float4*>(&Bs[k][tx * TN]);
            *reinterpret_cast<float4*>(&bb[4]) = *reinterpret_cast<const float4*>(&Bs[k][tx * TN + 4]);
#pragma unroll
            for (int i = 0; i < TM; i++)
#pragma unroll
                for (int j = 0; j < TN; j++)
                    acc[i][j] = fmaf(a[i], bb[j], acc[i][j]);
        }
        __syncthreads();
    }

    const float scale = clf_w[0];
    const float offs  = clf_b[0];
    float* Ob = out + (size_t)b * SEQ * SEQ;
    const int i0 = bi * BM + ty * TM;
    const int j0 = bj * BN + tx * TN;

    // Normal (upper) tile write: rows i, contiguous cols j
#pragma unroll
    for (int i = 0; i < TM; i++) {
        float4 r0, r1;
        r0.x = fmaf(acc[i][0], scale, offs);
        r0.y = fmaf(acc[i][1], scale, offs);
        r0.z = fmaf(acc[i][2], scale, offs);
        r0.w = fmaf(acc[i][3], scale, offs);
        r1.x = fmaf(acc[i][4], scale, offs);
        r1.y = fmaf(acc[i][5], scale, offs);
        r1.z = fmaf(acc[i][6], scale, offs);
        r1.w = fmaf(acc[i][7], scale, offs);
        *reinterpret_cast<float4*>(&Ob[(size_t)(i0 + i) * SEQ + j0])     = r0;
        *reinterpret_cast<float4*>(&Ob[(size_t)(i0 + i) * SEQ + j0 + 4]) = r1;
    }

    // Mirror write for off-diagonal tiles: rows j, contiguous cols i
    if (bi != bj) {
#pragma unroll
        for (int j = 0; j < TN; j++) {
            float4 m0, m1;
            m0.x = fmaf(acc[0][j], scale, offs);
            m0.y = fmaf(acc[1][j], scale, offs);
            m0.z = fmaf(acc[2][j], scale, offs);
            m0.w = fmaf(acc[3][j], scale, offs);
            m1.x = fmaf(acc[4][j], scale, offs);
            m1.y = fmaf(acc[5][j], scale, offs);
            m1.z = fmaf(acc[6][j], scale, offs);
            m1.w = fmaf(acc[7][j], scale, offs);
            *reinterpret_cast<float4*>(&Ob[(size_t)(j0 + j) * SEQ + i0])     = m0;
            *reinterpret_cast<float4*>(&Ob[(size_t)(j0 + j) * SEQ + i0 + 4]) = m1;
        }
    }
}

extern "C" void kernel_launch(void* const* d_in, const int* in_sizes, int n_in,
                              void* d_out, int out_size)
{
    const float* hs = (const float*)d_in[0];   // [4, 2048, 1024]
    const float* pw = (const float*)d_in[1];   // [256, 1024]
    const float* pb = (const float*)d_in[2];   // [256]
    const float* cw = (const float*)d_in[3];   // [1, 1]
    const float* cb = (const float*)d_in[4];   // [1]
    float* out = (float*)d_out;                // [4, 2048, 2048]

    // GEMM1: M=8192 rows of hs, N=256 cols -> grid (8192/128, 256/128)
    dim3 grid1(BATCH * SEQ / BM, DPROJ / BN);
    proj_relu_kernel<<<grid1, NTHREADS>>>(hs, pw, pb);

    // GEMM2: 136 upper-triangular tiles per batch, 4 batches
    dim3 grid2(136, BATCH);
    score_kernel<<<grid2, NTHREADS>>>(cw, cb, out);
}

// round 4
// speedup vs baseline: 2.1017x; 2.1017x over previous
#include <cuda_runtime.h>
#include <cuda_bf16.h>
#include <cstdint>

// ---------------------------------------------------------------------------
// Problem constants
// ---------------------------------------------------------------------------
#define BATCH  4
#define SEQ    2048
#define DMODEL 1024
#define DPROJ  256

// GEMM tiling
#define BM 128
#define BN 128
#define BK 32
#define NTHREADS 256          // 8 warps; warp grid 2 (m) x 4 (n); warp tile 64x32

// SMEM: 4 tiles (Ah, Al, Bh, Bl) per stage, 128 rows x 32 bf16, 80B row pitch
#define ROWB    80
#define TILE_B  (128 * ROWB)       // 10240
#define STAGE_B (4 * TILE_B)       // 40960
#define SMEM_B  (2 * STAGE_B)      // 81920 (also covers 128x132 f32 transpose = 67584)

// ---------------------------------------------------------------------------
// Device scratch (allocation-guard-safe)
// ---------------------------------------------------------------------------
__device__ __nv_bfloat16 g_hs_hi[BATCH * SEQ * DMODEL];
__device__ __nv_bfloat16 g_hs_lo[BATCH * SEQ * DMODEL];
__device__ __nv_bfloat16 g_pw_hi[DPROJ * DMODEL];
__device__ __nv_bfloat16 g_pw_lo[DPROJ * DMODEL];
__device__ __nv_bfloat16 g_h_hi[BATCH * SEQ * DPROJ];
__device__ __nv_bfloat16 g_h_lo[BATCH * SEQ * DPROJ];

// ---------------------------------------------------------------------------
// PTX helpers (baseline sm_80+ features only — no arch-'a' instructions)
// ---------------------------------------------------------------------------
__device__ __forceinline__ uint32_t smem_u32(const void* p) {
    uint32_t a;
    asm("{ .reg .u64 t; cvta.to.shared.u64 t, %1; cvt.u32.u64 %0, t; }" : "=r"(a) : "l"(p));
    return a;
}

__device__ __forceinline__ void cp16(uint32_t saddr, const void* g) {
    asm volatile("cp.async.cg.shared.global [%0], [%1], 16;" :: "r"(saddr), "l"(g));
}
#define CP_COMMIT()  asm volatile("cp.async.commit_group;" ::: "memory")
#define CP_WAIT_1()  asm volatile("cp.async.wait_group 1;" ::: "memory")
#define CP_WAIT_0()  asm volatile("cp.async.wait_group 0;" ::: "memory")

__device__ __forceinline__ void ldsm4(uint32_t a, uint32_t r[4]) {
    asm volatile("ldmatrix.sync.aligned.m8n8.x4.shared.b16 {%0,%1,%2,%3}, [%4];"
        : "=r"(r[0]), "=r"(r[1]), "=r"(r[2]), "=r"(r[3]) : "r"(a));
}

__device__ __forceinline__ void mma16816(float c[4], const uint32_t a[4],
                                         uint32_t b0, uint32_t b1) {
    asm volatile(
        "mma.sync.aligned.m16n8k16.row.col.f32.bf16.bf16.f32 "
        "{%0,%1,%2,%3}, {%4,%5,%6,%7}, {%8,%9}, {%0,%1,%2,%3};"
        : "+f"(c[0]), "+f"(c[1]), "+f"(c[2]), "+f"(c[3])
        : "r"(a[0]), "r"(a[1]), "r"(a[2]), "r"(a[3]), "r"(b0), "r"(b1));
}

// Issue cp.async for one 128x32 bf16 tile (col offset already applied by caller)
__device__ __forceinline__ void load_tile_async(uint32_t sbase,
                                                const __nv_bfloat16* __restrict__ src,
                                                int ld, int tid) {
#pragma unroll
    for (int q = 0; q < 2; q++) {
        int idx = tid + q * NTHREADS;   // 0..511
        int row = idx >> 2;
        int c   = idx & 3;
        cp16(sbase + row * ROWB + c * 16, src + (size_t)row * ld + c * 8);
    }
}

// One BK=32 chunk of the 3-product compensated MMA (acc += AhBh + AlBh + AhBl)
__device__ __forceinline__ void compute_chunk(uint32_t stage_base, int lane,
                                              int wm, int wn, float acc[4][4][4]) {
    const uint32_t aH = stage_base;
    const uint32_t aL = stage_base + TILE_B;
    const uint32_t bH = stage_base + 2 * TILE_B;
    const uint32_t bL = stage_base + 3 * TILE_B;
#pragma unroll
    for (int ks = 0; ks < 2; ks++) {
        uint32_t ah[4][4], al[4][4];
#pragma unroll
        for (int mf = 0; mf < 4; mf++) {
            int r = wm * 64 + mf * 16 + (lane & 15);
            uint32_t off = r * ROWB + ks * 32 + ((lane >> 4) << 4);
            ldsm4(aH + off, ah[mf]);
            ldsm4(aL + off, al[mf]);
        }
        uint32_t bh[2][4], bl[2][4];
#pragma unroll
        for (int np = 0; np < 2; np++) {
            int n = wn * 32 + np * 16 + (lane & 7) + ((lane >> 4) << 3);
            uint32_t off = n * ROWB + ks * 32 + (((lane >> 3) & 1) << 4);
            ldsm4(bH + off, bh[np]);
            ldsm4(bL + off, bl[np]);
        }
#pragma unroll
        for (int mf = 0; mf < 4; mf++)
#pragma unroll
            for (int nf = 0; nf < 4; nf++) {
                uint32_t b0h = bh[nf >> 1][(nf & 1) * 2], b1h = bh[nf >> 1][(nf & 1) * 2 + 1];
                uint32_t b0l = bl[nf >> 1][(nf & 1) * 2], b1l = bl[nf >> 1][(nf & 1) * 2 + 1];
                mma16816(acc[mf][nf], ah[mf], b0h, b1h);
                mma16816(acc[mf][nf], al[mf], b0h, b1h);
                mma16816(acc[mf][nf], ah[mf], b0l, b1l);
            }
    }
}

// ---------------------------------------------------------------------------
// Kernel 0: fp32 -> (hi, lo) bf16 split
// ---------------------------------------------------------------------------
__global__ __launch_bounds__(256)
void split_kernel(const float* __restrict__ src,
                  __nv_bfloat16* __restrict__ hi,
                  __nv_bfloat16* __restrict__ lo, int n4)
{
    int i = blockIdx.x * blockDim.x + threadIdx.x;
    if (i >= n4) return;
    float4 v = reinterpret_cast<const float4*>(src)[i];
    __nv_bfloat16 h0 = __float2bfloat16(v.x), h1 = __float2bfloat16(v.y);
    __nv_bfloat16 h2 = __float2bfloat16(v.z), h3 = __float2bfloat16(v.w);
    __nv_bfloat16 l0 = __float2bfloat16(v.x - __bfloat162float(h0));
    __nv_bfloat16 l1 = __float2bfloat16(v.y - __bfloat162float(h1));
    __nv_bfloat16 l2 = __float2bfloat16(v.z - __bfloat162float(h2));
    __nv_bfloat16 l3 = __float2bfloat16(v.w - __bfloat162float(h3));
    __nv_bfloat162 hp0(h0, h1), hp1(h2, h3), lp0(l0, l1), lp1(l2, l3);
    uint2 hv, lv;
    hv.x = *reinterpret_cast<uint32_t*>(&hp0); hv.y = *reinterpret_cast<uint32_t*>(&hp1);
    lv.x = *reinterpret_cast<uint32_t*>(&lp0); lv.y = *reinterpret_cast<uint32_t*>(&lp1);
    reinterpret_cast<uint2*>(hi)[i] = hv;
    reinterpret_cast<uint2*>(lo)[i] = lv;
}

// ---------------------------------------------------------------------------
// Kernel 1: h = relu(hs @ W^T + b), HMMA, output re-split to bf16 hi/lo
// grid = (8192/128, 256/128)
// ---------------------------------------------------------------------------
__global__ __launch_bounds__(NTHREADS, 1)
void proj_mma_kernel(const float* __restrict__ bias)
{
    extern __shared__ char smem[];
    const uint32_t sb = smem_u32(smem);
    const int tid = threadIdx.x, lane = tid & 31, wid = tid >> 5;
    const int wm = wid & 1, wn = wid >> 1;

    const __nv_bfloat16* Ah = g_hs_hi + (size_t)blockIdx.x * BM * DMODEL;
    const __nv_bfloat16* Al = g_hs_lo + (size_t)blockIdx.x * BM * DMODEL;
    const __nv_bfloat16* Bh = g_pw_hi + (size_t)blockIdx.y * BN * DMODEL;
    const __nv_bfloat16* Bl = g_pw_lo + (size_t)blockIdx.y * BN * DMODEL;

    float acc[4][4][4];
#pragma unroll
    for (int a = 0; a < 4; a++)
#pragma unroll
        for (int b = 0; b < 4; b++)
#pragma unroll
            for (int c = 0; c < 4; c++) acc[a][b][c] = 0.0f;

    const int NCHUNK = DMODEL / BK;   // 32

    // prefetch chunk 0 into stage 0
    {
        uint32_t s0 = sb;
        load_tile_async(s0,              Ah, DMODEL, tid);
        load_tile_async(s0 + TILE_B,     Al, DMODEL, tid);
        load_tile_async(s0 + 2 * TILE_B, Bh, DMODEL, tid);
        load_tile_async(s0 + 3 * TILE_B, Bl, DMODEL, tid);
        CP_COMMIT();
    }

    for (int kc = 0; kc < NCHUNK; kc++) {
        if (kc + 1 < NCHUNK) {
            uint32_t sn = sb + ((kc + 1) & 1) * STAGE_B;
            int koff = (kc + 1) * BK;
            load_tile_async(sn,              Ah + koff, DMODEL, tid);
            load_tile_async(sn + TILE_B,     Al + koff, DMODEL, tid);
            load_tile_async(sn + 2 * TILE_B, Bh + koff, DMODEL, tid);
            load_tile_async(sn + 3 * TILE_B, Bl + koff, DMODEL, tid);
            CP_COMMIT();
            CP_WAIT_1();
        } else {
            CP_WAIT_0();
        }
        __syncthreads();
        compute_chunk(sb + (kc & 1) * STAGE_B, lane, wm, wn, acc);
        __syncthreads();
    }

    // Epilogue: +bias, relu, split to bf16 hi/lo
    const int r0 = blockIdx.x * BM + wm * 64;
    const int c0 = blockIdx.y * BN + wn * 32;
#pragma unroll
    for (int mf = 0; mf < 4; mf++) {
        int row = r0 + mf * 16 + (lane >> 2);
#pragma unroll
        for (int nf = 0; nf < 4; nf++) {
            int col = c0 + nf * 8 + (lane & 3) * 2;
            float b0 = __ldg(bias + col), b1 = __ldg(bias + col + 1);
#pragma unroll
            for (int half = 0; half < 2; half++) {
                int r = row + half * 8;
                float v0 = fmaxf(acc[mf][nf][half * 2]     + b0, 0.0f);
                float v1 = fmaxf(acc[mf][nf][half * 2 + 1] + b1, 0.0f);
                __nv_bfloat16 h0 = __float2bfloat16(v0);
                __nv_bfloat16 h1 = __float2bfloat16(v1);
                __nv_bfloat16 l0 = __float2bfloat16(v0 - __bfloat162float(h0));
                __nv_bfloat16 l1 = __float2bfloat16(v1 - __bfloat162float(h1));
                __nv_bfloat162 hh(h0, h1), ll(l0, l1);
                *reinterpret_cast<__nv_bfloat162*>(g_h_hi + (size_t)r * DPROJ + col) = hh;
                *reinterpret_cast<__nv_bfloat162*>(g_h_lo + (size_t)r * DPROJ + col) = ll;
            }
        }
    }
}

// ---------------------------------------------------------------------------
// Kernel 2: scores[b] = (h_b @ h_b^T) * scale + offs, symmetric tiles
// grid = (136, BATCH)
// ---------------------------------------------------------------------------
__global__ __launch_bounds__(NTHREADS, 1)
void score_mma_kernel(const float* __restrict__ clf_w,
                      const float* __restrict__ clf_b,
                      float* __restrict__ out)
{
    extern __shared__ char smem[];
    const uint32_t sb = smem_u32(smem);
    const int tid = threadIdx.x, lane = tid & 31, wid = tid >> 5;
    const int wm = wid & 1, wn = wid >> 1;

    // decode upper-triangular tile (bi <= bj), 16x16 tile grid
    int t = blockIdx.x, bi = 0, rem = SEQ / BM;
    while (t >= rem) { t -= rem; bi++; rem--; }
    const int bj = bi + t;
    const int bb = blockIdx.y;

    const __nv_bfloat16* Hh = g_h_hi + (size_t)bb * SEQ * DPROJ;
    const __nv_bfloat16* Hl = g_h_lo + (size_t)bb * SEQ * DPROJ;
    const __nv_bfloat16* Ah = Hh + (size_t)bi * BM * DPROJ;
    const __nv_bfloat16* Al = Hl + (size_t)bi * BM * DPROJ;
    const __nv_bfloat16* Bh = Hh + (size_t)bj * BN * DPROJ;
    const __nv_bfloat16* Bl = Hl + (size_t)bj * BN * DPROJ;

    float acc[4][4][4];
#pragma unroll
    for (int a = 0; a < 4; a++)
#pragma unroll
        for (int b = 0; b < 4; b++)
#pragma unroll
            for (int c = 0; c < 4; c++) acc[a][b][c] = 0.0f;

    const int NCHUNK = DPROJ / BK;   // 8

    {
        uint32_t s0 = sb;
        load_tile_async(s0,              Ah, DPROJ, tid);
        load_tile_async(s0 + TILE_B,     Al, DPROJ, tid);
        load_tile_async(s0 + 2 * TILE_B, Bh, DPROJ, tid);
        load_tile_async(s0 + 3 * TILE_B, Bl, DPROJ, tid);
        CP_COMMIT();
    }

    for (int kc = 0; kc < NCHUNK; kc++) {
        if (kc + 1 < NCHUNK) {
            uint32_t sn = sb + ((kc + 1) & 1) * STAGE_B;
            int koff = (kc + 1) * BK;
            load_tile_async(sn,              Ah + koff, DPROJ, tid);
            load_tile_async(sn + TILE_B,     Al + koff, DPROJ, tid);
            load_tile_async(sn + 2 * TILE_B, Bh + koff, DPROJ, tid);
            load_tile_async(sn + 3 * TILE_B, Bl + koff, DPROJ, tid);
            CP_COMMIT();
            CP_WAIT_1();
        } else {
            CP_WAIT_0();
        }
        __syncthreads();
        compute_chunk(sb + (kc & 1) * STAGE_B, lane, wm, wn, acc);
        __syncthreads();
    }

    const float scale = __ldg(clf_w);
    const float offs  = __ldg(clf_b);
    float* Ob = out + (size_t)bb * SEQ * SEQ;
    const int i0 = bi * BM, j0 = bj * BN;

    // Normal (upper) tile: direct coalesced float2 stores from fragments
#pragma unroll
    for (int mf = 0; mf < 4; mf++) {
        int row = i0 + wm * 64 + mf * 16 + (lane >> 2);
#pragma unroll
        for (int nf = 0; nf < 4; nf++) {
            int col = j0 + wn * 32 + nf * 8 + (lane & 3) * 2;
#pragma unroll
            for (int half = 0; half < 2; half++) {
                float2 v;
                v.x = fmaf(acc[mf][nf][half * 2],     scale, offs);
                v.y = fmaf(acc[mf][nf][half * 2 + 1], scale, offs);
                *reinterpret_cast<float2*>(Ob + (size_t)(row + half * 8) * SEQ + col) = v;
            }
        }
    }

    // Mirror tile via padded-SMEM transpose (conflict-free, coalesced writes)
    if (bi != bj) {
        float* ts = reinterpret_cast<float*>(smem);   // [128][132]
        __syncthreads();   // mainloop smem no longer needed by any warp
#pragma unroll
        for (int mf = 0; mf < 4; mf++) {
            int rr = wm * 64 + mf * 16 + (lane >> 2);
#pragma unroll
            for (int nf = 0; nf < 4; nf++) {
                int cc = wn * 32 + nf * 8 + (lane & 3) * 2;
#pragma unroll
                for (int half = 0; half < 2; half++) {
                    int r = rr + half * 8;
                    ts[r * 132 + cc]     = fmaf(acc[mf][nf][half * 2],     scale, offs);
                    ts[r * 132 + cc + 1] = fmaf(acc[mf][nf][half * 2 + 1], scale, offs);
                }
            }
        }
        __syncthreads();
#pragma unroll
        for (int q = 0; q < 64; q++) {
            int linear = q * NTHREADS + tid;
            int jj = linear >> 7;        // mirror row (orig col)
            int ii = linear & 127;       // mirror col (orig row)
            Ob[(size_t)(j0 + jj) * SEQ + i0 + ii] = ts[ii * 132 + jj];
        }
    }
}

// ---------------------------------------------------------------------------
// Launch
// ---------------------------------------------------------------------------
extern "C" void kernel_launch(void* const* d_in, const int* in_sizes, int n_in,
                              void* d_out, int out_size)
{
    const float* hs = (const float*)d_in[0];   // [4, 2048, 1024]
    const float* pw = (const float*)d_in[1];   // [256, 1024]
    const float* pb = (const float*)d_in[2];   // [256]
    const float* cw = (const float*)d_in[3];   // [1, 1]
    const float* cb = (const float*)d_in[4];   // [1]
    float* out = (float*)d_out;                // [4, 2048, 2048]

    cudaFuncSetAttribute(proj_mma_kernel,  cudaFuncAttributeMaxDynamicSharedMemorySize, SMEM_B);
    cudaFuncSetAttribute(score_mma_kernel, cudaFuncAttributeMaxDynamicSharedMemorySize, SMEM_B);

    __nv_bfloat16 *hs_hi, *hs_lo, *pw_hi, *pw_lo;
    cudaGetSymbolAddress((void**)&hs_hi, g_hs_hi);
    cudaGetSymbolAddress((void**)&hs_lo, g_hs_lo);
    cudaGetSymbolAddress((void**)&pw_hi, g_pw_hi);
    cudaGetSymbolAddress((void**)&pw_lo, g_pw_lo);

    int n4_hs = BATCH * SEQ * DMODEL / 4;
    int n4_pw = DPROJ * DMODEL / 4;
    split_kernel<<<(n4_hs + 255) / 256, 256>>>(hs, hs_hi, hs_lo, n4_hs);
    split_kernel<<<(n4_pw + 255) / 256, 256>>>(pw, pw_hi, pw_lo, n4_pw);

    dim3 grid1(BATCH * SEQ / BM, DPROJ / BN);     // (64, 2)
    proj_mma_kernel<<<grid1, NTHREADS, SMEM_B>>>(pb);

    dim3 grid2(136, BATCH);
    score_mma_kernel<<<grid2, NTHREADS, SMEM_B>>>(cw, cb, out);
}

// round 5
// speedup vs baseline: 2.2487x; 1.0700x over previous
#include <cuda_runtime.h>
#include <cuda_bf16.h>
#include <cstdint>

// ---------------------------------------------------------------------------
// Problem constants
// ---------------------------------------------------------------------------
#define BATCH  4
#define SEQ    2048
#define DMODEL 1024
#define DPROJ  256

#define BK    32
#define ROWB  80                    // 32 bf16 = 64B payload + 16B skew

// proj: BM=128, BN=64, 256 threads (8 warps, 4x2), 3 stages
#define PJ_STAGE_ROWS 384           // Ah128 + Al128 + Bh64 + Bl64
#define PJ_STAGE_B    (PJ_STAGE_ROWS * ROWB)        // 30720
#define PJ_SMEM       (3 * PJ_STAGE_B)              // 92160

// score: BM=128, BN=128, 512 threads (16 warps, 4x4), 3 stages
#define SC_STAGE_ROWS 512
#define SC_STAGE_B    (SC_STAGE_ROWS * ROWB)        // 40960
#define SC_SMEM       (3 * SC_STAGE_B)              // 122880

// ---------------------------------------------------------------------------
// Device scratch
// ---------------------------------------------------------------------------
__device__ __nv_bfloat16 g_hs_hi[BATCH * SEQ * DMODEL];
__device__ __nv_bfloat16 g_hs_lo[BATCH * SEQ * DMODEL];
__device__ __nv_bfloat16 g_pw_hi[DPROJ * DMODEL];
__device__ __nv_bfloat16 g_pw_lo[DPROJ * DMODEL];
__device__ __nv_bfloat16 g_h_hi[BATCH * SEQ * DPROJ];
__device__ __nv_bfloat16 g_h_lo[BATCH * SEQ * DPROJ];

// ---------------------------------------------------------------------------
// PTX helpers (baseline sm_80+ features only)
// ---------------------------------------------------------------------------
__device__ __forceinline__ uint32_t smem_u32(const void* p) {
    uint32_t a;
    asm("{ .reg .u64 t; cvta.to.shared.u64 t, %1; cvt.u32.u64 %0, t; }" : "=r"(a) : "l"(p));
    return a;
}

__device__ __forceinline__ void cp16(uint32_t saddr, const void* g) {
    asm volatile("cp.async.cg.shared.global [%0], [%1], 16;" :: "r"(saddr), "l"(g));
}
#define CP_COMMIT() asm volatile("cp.async.commit_group;" ::: "memory")
#define CP_WAIT_1() asm volatile("cp.async.wait_group 1;" ::: "memory")

__device__ __forceinline__ void ldsm4(uint32_t a, uint32_t r[4]) {
    asm volatile("ldmatrix.sync.aligned.m8n8.x4.shared.b16 {%0,%1,%2,%3}, [%4];"
        : "=r"(r[0]), "=r"(r[1]), "=r"(r[2]), "=r"(r[3]) : "r"(a));
}

__device__ __forceinline__ void mma16816(float c[4], const uint32_t a[4],
                                         uint32_t b0, uint32_t b1) {
    asm volatile(
        "mma.sync.aligned.m16n8k16.row.col.f32.bf16.bf16.f32 "
        "{%0,%1,%2,%3}, {%4,%5,%6,%7}, {%8,%9}, {%0,%1,%2,%3};"
        : "+f"(c[0]), "+f"(c[1]), "+f"(c[2]), "+f"(c[3])
        : "r"(a[0]), "r"(a[1]), "r"(a[2]), "r"(a[3]), "r"(b0), "r"(b1));
}

// cp.async one tile of ROWS x 32 bf16 into SMEM (80B pitch)
template<int ROWS, int NT>
__device__ __forceinline__ void load_rows(uint32_t sbase,
                                          const __nv_bfloat16* __restrict__ src,
                                          int ld, int tid) {
#pragma unroll
    for (int idx = tid; idx < ROWS * 4; idx += NT) {
        int row = idx >> 2, c = idx & 3;
        cp16(sbase + row * ROWB + c * 16, src + (size_t)row * ld + c * 8);
    }
}

// One BK=32 chunk: warp tile 32x32, 3-product compensated (AhBh+AlBh+AhBl)
__device__ __forceinline__ void compute32(uint32_t aH, uint32_t aL,
                                          uint32_t bH, uint32_t bL,
                                          int lane, int wm, int wn,
                                          float acc[2][4][4]) {
#pragma unroll
    for (int ks = 0; ks < 2; ks++) {
        uint32_t ah[2][4], al[2][4];
#pragma unroll
        for (int mf = 0; mf < 2; mf++) {
            int r = wm * 32 + mf * 16 + (lane & 15);
            uint32_t off = r * ROWB + ks * 32 + ((lane >> 4) << 4);
            ldsm4(aH + off, ah[mf]);
            ldsm4(aL + off, al[mf]);
        }
        uint32_t bh[2][4], bl[2][4];
#pragma unroll
        for (int np = 0; np < 2; np++) {
            int n = wn * 32 + np * 16 + (lane & 7) + ((lane >> 4) << 3);
            uint32_t off = n * ROWB + ks * 32 + (((lane >> 3) & 1) << 4);
            ldsm4(bH + off, bh[np]);
            ldsm4(bL + off, bl[np]);
        }
#pragma unroll
        for (int mf = 0; mf < 2; mf++)
#pragma unroll
            for (int nf = 0; nf < 4; nf++) {
                uint32_t b0h = bh[nf >> 1][(nf & 1) * 2], b1h = bh[nf >> 1][(nf & 1) * 2 + 1];
                uint32_t b0l = bl[nf >> 1][(nf & 1) * 2], b1l = bl[nf >> 1][(nf & 1) * 2 + 1];
                mma16816(acc[mf][nf], ah[mf], b0h, b1h);
                mma16816(acc[mf][nf], al[mf], b0h, b1h);
                mma16816(acc[mf][nf], ah[mf], b0l, b1l);
            }
    }
}

// ---------------------------------------------------------------------------
// Kernel 0: fp32 -> (hi, lo) bf16 split
// ---------------------------------------------------------------------------
__global__ __launch_bounds__(256)
void split_kernel(const float* __restrict__ src,
                  __nv_bfloat16* __restrict__ hi,
                  __nv_bfloat16* __restrict__ lo, int n4)
{
    int i = blockIdx.x * blockDim.x + threadIdx.x;
    if (i >= n4) return;
    float4 v = reinterpret_cast<const float4*>(src)[i];
    __nv_bfloat16 h0 = __float2bfloat16(v.x), h1 = __float2bfloat16(v.y);
    __nv_bfloat16 h2 = __float2bfloat16(v.z), h3 = __float2bfloat16(v.w);
    __nv_bfloat16 l0 = __float2bfloat16(v.x - __bfloat162float(h0));
    __nv_bfloat16 l1 = __float2bfloat16(v.y - __bfloat162float(h1));
    __nv_bfloat16 l2 = __float2bfloat16(v.z - __bfloat162float(h2));
    __nv_bfloat16 l3 = __float2bfloat16(v.w - __bfloat162float(h3));
    __nv_bfloat162 hp0(h0, h1), hp1(h2, h3), lp0(l0, l1), lp1(l2, l3);
    uint2 hv, lv;
    hv.x = *reinterpret_cast<uint32_t*>(&hp0); hv.y = *reinterpret_cast<uint32_t*>(&hp1);
    lv.x = *reinterpret_cast<uint32_t*>(&lp0); lv.y = *reinterpret_cast<uint32_t*>(&lp1);
    reinterpret_cast<uint2*>(hi)[i] = hv;
    reinterpret_cast<uint2*>(lo)[i] = lv;
}

// ---------------------------------------------------------------------------
// Kernel 1: h = relu(hs @ W^T + b)   BM=128 BN=64, grid (64,4), 256 thr
// ---------------------------------------------------------------------------
__global__ __launch_bounds__(256, 2)
void proj_mma_kernel(const float* __restrict__ bias)
{
    extern __shared__ char smem[];
    const uint32_t sb = smem_u32(smem);
    const int tid = threadIdx.x, lane = tid & 31, wid = tid >> 5;
    const int wm = wid & 3, wn = wid >> 2;   // 4 x 2 warp grid

    const __nv_bfloat16* Ah = g_hs_hi + (size_t)blockIdx.x * 128 * DMODEL;
    const __nv_bfloat16* Al = g_hs_lo + (size_t)blockIdx.x * 128 * DMODEL;
    const __nv_bfloat16* Bh = g_pw_hi + (size_t)blockIdx.y * 64 * DMODEL;
    const __nv_bfloat16* Bl = g_pw_lo + (size_t)blockIdx.y * 64 * DMODEL;

    float acc[2][4][4];
#pragma unroll
    for (int a = 0; a < 2; a++)
#pragma unroll
        for (int b = 0; b < 4; b++)
#pragma unroll
            for (int c = 0; c < 4; c++) acc[a][b][c] = 0.0f;

    const int NCHUNK = DMODEL / BK;   // 32

    // prologue: chunks 0, 1 into stages 0, 1
#pragma unroll
    for (int p = 0; p < 2; p++) {
        uint32_t s = sb + p * PJ_STAGE_B;
        int ko = p * BK;
        load_rows<128, 256>(s,                   Ah + ko, DMODEL, tid);
        load_rows<128, 256>(s + 128 * ROWB,      Al + ko, DMODEL, tid);
        load_rows< 64, 256>(s + 256 * ROWB,      Bh + ko, DMODEL, tid);
        load_rows< 64, 256>(s + 320 * ROWB,      Bl + ko, DMODEL, tid);
        CP_COMMIT();
    }

    int st = 0, pf = 2 % 3;
    for (int kc = 0; kc < NCHUNK; kc++) {
        CP_WAIT_1();
        __syncthreads();
        if (kc + 2 < NCHUNK) {
            uint32_t s = sb + pf * PJ_STAGE_B;
            int ko = (kc + 2) * BK;
            load_rows<128, 256>(s,              Ah + ko, DMODEL, tid);
            load_rows<128, 256>(s + 128 * ROWB, Al + ko, DMODEL, tid);
            load_rows< 64, 256>(s + 256 * ROWB, Bh + ko, DMODEL, tid);
            load_rows< 64, 256>(s + 320 * ROWB, Bl + ko, DMODEL, tid);
        }
        CP_COMMIT();
        uint32_t sc = sb + st * PJ_STAGE_B;
        compute32(sc, sc + 128 * ROWB, sc + 256 * ROWB, sc + 320 * ROWB,
                  lane, wm, wn, acc);
        st = (st + 1 == 3) ? 0 : st + 1;
        pf = (pf + 1 == 3) ? 0 : pf + 1;
    }

    // Epilogue: +bias, relu, split to bf16 hi/lo
    const int r0 = blockIdx.x * 128 + wm * 32;
    const int c0 = blockIdx.y * 64 + wn * 32;
#pragma unroll
    for (int mf = 0; mf < 2; mf++) {
        int row = r0 + mf * 16 + (lane >> 2);
#pragma unroll
        for (int nf = 0; nf < 4; nf++) {
            int col = c0 + nf * 8 + (lane & 3) * 2;
            float b0 = __ldg(bias + col), b1 = __ldg(bias + col + 1);
#pragma unroll
            for (int half = 0; half < 2; half++) {
                int r = row + half * 8;
                float v0 = fmaxf(acc[mf][nf][half * 2]     + b0, 0.0f);
                float v1 = fmaxf(acc[mf][nf][half * 2 + 1] + b1, 0.0f);
                __nv_bfloat16 h0 = __float2bfloat16(v0);
                __nv_bfloat16 h1 = __float2bfloat16(v1);
                __nv_bfloat16 l0 = __float2bfloat16(v0 - __bfloat162float(h0));
                __nv_bfloat16 l1 = __float2bfloat16(v1 - __bfloat162float(h1));
                __nv_bfloat162 hh(h0, h1), ll(l0, l1);
                *reinterpret_cast<__nv_bfloat162*>(g_h_hi + (size_t)r * DPROJ + col) = hh;
                *reinterpret_cast<__nv_bfloat162*>(g_h_lo + (size_t)r * DPROJ + col) = ll;
            }
        }
    }
}

// ---------------------------------------------------------------------------
// Kernel 2: scores = (h @ h^T)*scale + offs   BM=BN=128, grid (136,4), 512 thr
// ---------------------------------------------------------------------------
__global__ __launch_bounds__(512, 1)
void score_mma_kernel(const float* __restrict__ clf_w,
                      const float* __restrict__ clf_b,
                      float* __restrict__ out)
{
    extern __shared__ char smem[];
    const uint32_t sb = smem_u32(smem);
    const int tid = threadIdx.x, lane = tid & 31, wid = tid >> 5;
    const int wm = wid & 3, wn = wid >> 2;   // 4 x 4 warp grid

    int t = blockIdx.x, bi = 0, rem = SEQ / 128;
    while (t >= rem) { t -= rem; bi++; rem--; }
    const int bj = bi + t;
    const int bb = blockIdx.y;

    const __nv_bfloat16* Hh = g_h_hi + (size_t)bb * SEQ * DPROJ;
    const __nv_bfloat16* Hl = g_h_lo + (size_t)bb * SEQ * DPROJ;
    const __nv_bfloat16* Ah = Hh + (size_t)bi * 128 * DPROJ;
    const __nv_bfloat16* Al = Hl + (size_t)bi * 128 * DPROJ;
    const __nv_bfloat16* Bh = Hh + (size_t)bj * 128 * DPROJ;
    const __nv_bfloat16* Bl = Hl + (size_t)bj * 128 * DPROJ;

    float acc[2][4][4];
#pragma unroll
    for (int a = 0; a < 2; a++)
#pragma unroll
        for (int b = 0; b < 4; b++)
#pragma unroll
            for (int c = 0; c < 4; c++) acc[a][b][c] = 0.0f;

    const int NCHUNK = DPROJ / BK;   // 8

#pragma unroll
    for (int p = 0; p < 2; p++) {
        uint32_t s = sb + p * SC_STAGE_B;
        int ko = p * BK;
        load_rows<128, 512>(s,              Ah + ko, DPROJ, tid);
        load_rows<128, 512>(s + 128 * ROWB, Al + ko, DPROJ, tid);
        load_rows<128, 512>(s + 256 * ROWB, Bh + ko, DPROJ, tid);
        load_rows<128, 512>(s + 384 * ROWB, Bl + ko, DPROJ, tid);
        CP_COMMIT();
    }

    int st = 0, pf = 2;
    for (int kc = 0; kc < NCHUNK; kc++) {
        CP_WAIT_1();
        __syncthreads();
        if (kc + 2 < NCHUNK) {
            uint32_t s = sb + pf * SC_STAGE_B;
            int ko = (kc + 2) * BK;
            load_rows<128, 512>(s,              Ah + ko, DPROJ, tid);
            load_rows<128, 512>(s + 128 * ROWB, Al + ko, DPROJ, tid);
            load_rows<128, 512>(s + 256 * ROWB, Bh + ko, DPROJ, tid);
            load_rows<128, 512>(s + 384 * ROWB, Bl + ko, DPROJ, tid);
        }
        CP_COMMIT();
        uint32_t sc = sb + st * SC_STAGE_B;
        compute32(sc, sc + 128 * ROWB, sc + 256 * ROWB, sc + 384 * ROWB,
                  lane, wm, wn, acc);
        st = (st + 1 == 3) ? 0 : st + 1;
        pf = (pf + 1 == 3) ? 0 : pf + 1;
    }

    const float scale = __ldg(clf_w);
    const float offs  = __ldg(clf_b);
    float* Ob = out + (size_t)bb * SEQ * SEQ;
    const int i0 = bi * 128, j0 = bj * 128;

    // Upper tile: coalesced float2 stores straight from fragments
#pragma unroll
    for (int mf = 0; mf < 2; mf++) {
        int row = i0 + wm * 32 + mf * 16 + (lane >> 2);
#pragma unroll
        for (int nf = 0; nf < 4; nf++) {
            int col = j0 + wn * 32 + nf * 8 + (lane & 3) * 2;
#pragma unroll
            for (int half = 0; half < 2; half++) {
                float2 v;
                v.x = fmaf(acc[mf][nf][half * 2],     scale, offs);
                v.y = fmaf(acc[mf][nf][half * 2 + 1], scale, offs);
                *reinterpret_cast<float2*>(Ob + (size_t)(row + half * 8) * SEQ + col) = v;
            }
        }
    }

    // Mirror tile via padded-SMEM transpose (conflict-free, coalesced writes)
    if (bi != bj) {
        float* ts = reinterpret_cast<float*>(smem);   // [128][132]
        __syncthreads();
#pragma unroll
        for (int mf = 0; mf < 2; mf++) {
            int rr = wm * 32 + mf * 16 + (lane >> 2);
#pragma unroll
            for (int nf = 0; nf < 4; nf++) {
                int cc = wn * 32 + nf * 8 + (lane & 3) * 2;
#pragma unroll
                for (int half = 0; half < 2; half++) {
                    int r = rr + half * 8;
                    ts[r * 132 + cc]     = fmaf(acc[mf][nf][half * 2],     scale, offs);
                    ts[r * 132 + cc + 1] = fmaf(acc[mf][nf][half * 2 + 1], scale, offs);
                }
            }
        }
        __syncthreads();
#pragma unroll
        for (int q = 0; q < 32; q++) {
            int linear = q * 512 + tid;
            int jj = linear >> 7;
            int ii = linear & 127;
            Ob[(size_t)(j0 + jj) * SEQ + i0 + ii] = ts[ii * 132 + jj];
        }
    }
}

// ---------------------------------------------------------------------------
// Launch
// ---------------------------------------------------------------------------
extern "C" void kernel_launch(void* const* d_in, const int* in_sizes, int n_in,
                              void* d_out, int out_size)
{
    const float* hs = (const float*)d_in[0];
    const float* pw = (const float*)d_in[1];
    const float* pb = (const float*)d_in[2];
    const float* cw = (const float*)d_in[3];
    const float* cb = (const float*)d_in[4];
    float* out = (float*)d_out;

    cudaFuncSetAttribute(proj_mma_kernel,  cudaFuncAttributeMaxDynamicSharedMemorySize, PJ_SMEM);
    cudaFuncSetAttribute(score_mma_kernel, cudaFuncAttributeMaxDynamicSharedMemorySize, SC_SMEM);

    __nv_bfloat16 *hs_hi, *hs_lo, *pw_hi, *pw_lo;
    cudaGetSymbolAddress((void**)&hs_hi, g_hs_hi);
    cudaGetSymbolAddress((void**)&hs_lo, g_hs_lo);
    cudaGetSymbolAddress((void**)&pw_hi, g_pw_hi);
    cudaGetSymbolAddress((void**)&pw_lo, g_pw_lo);

    int n4_hs = BATCH * SEQ * DMODEL / 4;
    int n4_pw = DPROJ * DMODEL / 4;
    split_kernel<<<(n4_hs + 255) / 256, 256>>>(hs, hs_hi, hs_lo, n4_hs);
    split_kernel<<<(n4_pw + 255) / 256, 256>>>(pw, pw_hi, pw_lo, n4_pw);

    dim3 grid1(BATCH * SEQ / 128, DPROJ / 64);   // (64, 4)
    proj_mma_kernel<<<grid1, 256, PJ_SMEM>>>(pb);

    dim3 grid2(136, BATCH);
    score_mma_kernel<<<grid2, 512, SC_SMEM>>>(cw, cb, out);
}

// round 6
// speedup vs baseline: 2.3223x; 1.0327x over previous
#include <cuda_runtime.h>
#include <cuda_bf16.h>
#include <cstdint>

// ---------------------------------------------------------------------------
// Problem constants
// ---------------------------------------------------------------------------
#define BATCH  4
#define SEQ    2048
#define DMODEL 1024
#define DPROJ  256

#define BK    32
#define ROWB  80                    // 32 bf16 = 64B payload + 16B skew

// Both GEMMs: CTA tile 128x128, 4 warps (2x2), warp tile 64x64, 2 stages
#define STAGE_ROWS 512              // Ah128 + Al128 + Bh128 + Bl128
#define STAGE_B    (STAGE_ROWS * ROWB)   // 40960
#define SMEM_SZ    (2 * STAGE_B)         // 81920  (>= 128*133*4 transpose)

// ---------------------------------------------------------------------------
// Device scratch
// ---------------------------------------------------------------------------
__device__ __nv_bfloat16 g_hs_hi[BATCH * SEQ * DMODEL];
__device__ __nv_bfloat16 g_hs_lo[BATCH * SEQ * DMODEL];
__device__ __nv_bfloat16 g_pw_hi[DPROJ * DMODEL];
__device__ __nv_bfloat16 g_pw_lo[DPROJ * DMODEL];
__device__ __nv_bfloat16 g_h_hi[BATCH * SEQ * DPROJ];
__device__ __nv_bfloat16 g_h_lo[BATCH * SEQ * DPROJ];

// ---------------------------------------------------------------------------
// PTX helpers (baseline sm_80+ features only)
// ---------------------------------------------------------------------------
__device__ __forceinline__ uint32_t smem_u32(const void* p) {
    uint32_t a;
    asm("{ .reg .u64 t; cvta.to.shared.u64 t, %1; cvt.u32.u64 %0, t; }" : "=r"(a) : "l"(p));
    return a;
}

__device__ __forceinline__ void cp16(uint32_t saddr, const void* g) {
    asm volatile("cp.async.cg.shared.global [%0], [%1], 16;" :: "r"(saddr), "l"(g));
}
#define CP_COMMIT() asm volatile("cp.async.commit_group;" ::: "memory")
#define CP_WAIT_1() asm volatile("cp.async.wait_group 1;" ::: "memory")
#define CP_WAIT_0() asm volatile("cp.async.wait_group 0;" ::: "memory")

__device__ __forceinline__ void ldsm4(uint32_t a, uint32_t r[4]) {
    asm volatile("ldmatrix.sync.aligned.m8n8.x4.shared.b16 {%0,%1,%2,%3}, [%4];"
        : "=r"(r[0]), "=r"(r[1]), "=r"(r[2]), "=r"(r[3]) : "r"(a));
}

__device__ __forceinline__ void mma16816(float c[4], const uint32_t a[4],
                                         uint32_t b0, uint32_t b1) {
    asm volatile(
        "mma.sync.aligned.m16n8k16.row.col.f32.bf16.bf16.f32 "
        "{%0,%1,%2,%3}, {%4,%5,%6,%7}, {%8,%9}, {%0,%1,%2,%3};"
        : "+f"(c[0]), "+f"(c[1]), "+f"(c[2]), "+f"(c[3])
        : "r"(a[0]), "r"(a[1]), "r"(a[2]), "r"(a[3]), "r"(b0), "r"(b1));
}

// cp.async a full 512-row stage (Ah,Al,Bh,Bl each 128 rows x 32 bf16)
__device__ __forceinline__ void load_stage(uint32_t sbase,
                                           const __nv_bfloat16* __restrict__ Ah,
                                           const __nv_bfloat16* __restrict__ Al,
                                           const __nv_bfloat16* __restrict__ Bh,
                                           const __nv_bfloat16* __restrict__ Bl,
                                           int ld, int tid) {
#pragma unroll
    for (int q = 0; q < 4; q++) {
        int idx = tid + q * 128;     // 0..511 over one 128-row tile
        int row = idx >> 2, c = idx & 3;
        size_t go = (size_t)row * ld + c * 8;
        uint32_t so = row * ROWB + c * 16;
        cp16(sbase + so,                   Ah + go);
        cp16(sbase + 128 * ROWB + so,      Al + go);
        cp16(sbase + 256 * ROWB + so,      Bh + go);
        cp16(sbase + 384 * ROWB + so,      Bl + go);
    }
}

// One BK=32 chunk, warp tile 64x64, 3-product compensated (AhBh+AlBh+AhBl)
__device__ __forceinline__ void compute64(uint32_t stage, int lane,
                                          int wm, int wn, float acc[4][8][4]) {
    const uint32_t aH = stage;
    const uint32_t aL = stage + 128 * ROWB;
    const uint32_t bH = stage + 256 * ROWB;
    const uint32_t bL = stage + 384 * ROWB;
#pragma unroll
    for (int ks = 0; ks < 2; ks++) {
        uint32_t ah[4][4], al[4][4];
#pragma unroll
        for (int mf = 0; mf < 4; mf++) {
            int r = wm * 64 + mf * 16 + (lane & 15);
            uint32_t off = r * ROWB + ks * 32 + ((lane >> 4) << 4);
            ldsm4(aH + off, ah[mf]);
            ldsm4(aL + off, al[mf]);
        }
        uint32_t bh[4][4], bl[4][4];
#pragma unroll
        for (int np = 0; np < 4; np++) {
            int n = wn * 64 + np * 16 + (lane & 7) + ((lane >> 4) << 3);
            uint32_t off = n * ROWB + ks * 32 + (((lane >> 3) & 1) << 4);
            ldsm4(bH + off, bh[np]);
            ldsm4(bL + off, bl[np]);
        }
#pragma unroll
        for (int mf = 0; mf < 4; mf++)
#pragma unroll
            for (int nf = 0; nf < 8; nf++) {
                uint32_t b0h = bh[nf >> 1][(nf & 1) * 2], b1h = bh[nf >> 1][(nf & 1) * 2 + 1];
                uint32_t b0l = bl[nf >> 1][(nf & 1) * 2], b1l = bl[nf >> 1][(nf & 1) * 2 + 1];
                mma16816(acc[mf][nf], ah[mf], b0h, b1h);
                mma16816(acc[mf][nf], al[mf], b0h, b1h);
                mma16816(acc[mf][nf], ah[mf], b0l, b1l);
            }
    }
}

// ---------------------------------------------------------------------------
// Kernel 0: fp32 -> (hi, lo) bf16 split
// ---------------------------------------------------------------------------
__global__ __launch_bounds__(256)
void split_kernel(const float* __restrict__ src,
                  __nv_bfloat16* __restrict__ hi,
                  __nv_bfloat16* __restrict__ lo, int n4)
{
    int i = blockIdx.x * blockDim.x + threadIdx.x;
    if (i >= n4) return;
    float4 v = reinterpret_cast<const float4*>(src)[i];
    __nv_bfloat16 h0 = __float2bfloat16(v.x), h1 = __float2bfloat16(v.y);
    __nv_bfloat16 h2 = __float2bfloat16(v.z), h3 = __float2bfloat16(v.w);
    __nv_bfloat16 l0 = __float2bfloat16(v.x - __bfloat162float(h0));
    __nv_bfloat16 l1 = __float2bfloat16(v.y - __bfloat162float(h1));
    __nv_bfloat16 l2 = __float2bfloat16(v.z - __bfloat162float(h2));
    __nv_bfloat16 l3 = __float2bfloat16(v.w - __bfloat162float(h3));
    __nv_bfloat162 hp0(h0, h1), hp1(h2, h3), lp0(l0, l1), lp1(l2, l3);
    uint2 hv, lv;
    hv.x = *reinterpret_cast<uint32_t*>(&hp0); hv.y = *reinterpret_cast<uint32_t*>(&hp1);
    lv.x = *reinterpret_cast<uint32_t*>(&lp0); lv.y = *reinterpret_cast<uint32_t*>(&lp1);
    reinterpret_cast<uint2*>(hi)[i] = hv;
    reinterpret_cast<uint2*>(lo)[i] = lv;
}

// ---------------------------------------------------------------------------
// Kernel 1: h = relu(hs @ W^T + b)   CTA 128x128, grid (64,2), 128 thr
// ---------------------------------------------------------------------------
__global__ __launch_bounds__(128, 2)
void proj_mma_kernel(const float* __restrict__ bias)
{
    extern __shared__ char smem[];
    const uint32_t sb = smem_u32(smem);
    const int tid = threadIdx.x, lane = tid & 31, wid = tid >> 5;
    const int wm = wid & 1, wn = wid >> 1;

    const __nv_bfloat16* Ah = g_hs_hi + (size_t)blockIdx.x * 128 * DMODEL;
    const __nv_bfloat16* Al = g_hs_lo + (size_t)blockIdx.x * 128 * DMODEL;
    const __nv_bfloat16* Bh = g_pw_hi + (size_t)blockIdx.y * 128 * DMODEL;
    const __nv_bfloat16* Bl = g_pw_lo + (size_t)blockIdx.y * 128 * DMODEL;

    float acc[4][8][4];
#pragma unroll
    for (int a = 0; a < 4; a++)
#pragma unroll
        for (int b = 0; b < 8; b++)
#pragma unroll
            for (int c = 0; c < 4; c++) acc[a][b][c] = 0.0f;

    const int NCHUNK = DMODEL / BK;   // 32

    load_stage(sb, Ah, Al, Bh, Bl, DMODEL, tid);
    CP_COMMIT();

    for (int kc = 0; kc < NCHUNK; kc++) {
        if (kc + 1 < NCHUNK) {
            int ko = (kc + 1) * BK;
            load_stage(sb + ((kc + 1) & 1) * STAGE_B,
                       Ah + ko, Al + ko, Bh + ko, Bl + ko, DMODEL, tid);
            CP_COMMIT();
            CP_WAIT_1();
        } else {
            CP_WAIT_0();
        }
        __syncthreads();
        compute64(sb + (kc & 1) * STAGE_B, lane, wm, wn, acc);
        __syncthreads();
    }

    // Epilogue: +bias, relu, split to bf16 hi/lo
    const int r0 = blockIdx.x * 128 + wm * 64;
    const int c0 = blockIdx.y * 128 + wn * 64;
#pragma unroll
    for (int mf = 0; mf < 4; mf++) {
        int row = r0 + mf * 16 + (lane >> 2);
#pragma unroll
        for (int nf = 0; nf < 8; nf++) {
            int col = c0 + nf * 8 + (lane & 3) * 2;
            float b0 = __ldg(bias + col), b1 = __ldg(bias + col + 1);
#pragma unroll
            for (int half = 0; half < 2; half++) {
                int r = row + half * 8;
                float v0 = fmaxf(acc[mf][nf][half * 2]     + b0, 0.0f);
                float v1 = fmaxf(acc[mf][nf][half * 2 + 1] + b1, 0.0f);
                __nv_bfloat16 h0 = __float2bfloat16(v0);
                __nv_bfloat16 h1 = __float2bfloat16(v1);
                __nv_bfloat16 l0 = __float2bfloat16(v0 - __bfloat162float(h0));
                __nv_bfloat16 l1 = __float2bfloat16(v1 - __bfloat162float(h1));
                __nv_bfloat162 hh(h0, h1), ll(l0, l1);
                *reinterpret_cast<__nv_bfloat162*>(g_h_hi + (size_t)r * DPROJ + col) = hh;
                *reinterpret_cast<__nv_bfloat162*>(g_h_lo + (size_t)r * DPROJ + col) = ll;
            }
        }
    }
}

// ---------------------------------------------------------------------------
// Kernel 2: scores = (h @ h^T)*scale + offs   CTA 128x128, grid (136,4), 128 thr
// ---------------------------------------------------------------------------
__global__ __launch_bounds__(128, 2)
void score_mma_kernel(const float* __restrict__ clf_w,
                      const float* __restrict__ clf_b,
                      float* __restrict__ out)
{
    extern __shared__ char smem[];
    const uint32_t sb = smem_u32(smem);
    const int tid = threadIdx.x, lane = tid & 31, wid = tid >> 5;
    const int wm = wid & 1, wn = wid >> 1;

    int t = blockIdx.x, bi = 0, rem = SEQ / 128;
    while (t >= rem) { t -= rem; bi++; rem--; }
    const int bj = bi + t;
    const int bb = blockIdx.y;

    const __nv_bfloat16* Hh = g_h_hi + (size_t)bb * SEQ * DPROJ;
    const __nv_bfloat16* Hl = g_h_lo + (size_t)bb * SEQ * DPROJ;
    const __nv_bfloat16* Ah = Hh + (size_t)bi * 128 * DPROJ;
    const __nv_bfloat16* Al = Hl + (size_t)bi * 128 * DPROJ;
    const __nv_bfloat16* Bh = Hh + (size_t)bj * 128 * DPROJ;
    const __nv_bfloat16* Bl = Hl + (size_t)bj * 128 * DPROJ;

    float acc[4][8][4];
#pragma unroll
    for (int a = 0; a < 4; a++)
#pragma unroll
        for (int b = 0; b < 8; b++)
#pragma unroll
            for (int c = 0; c < 4; c++) acc[a][b][c] = 0.0f;

    const int NCHUNK = DPROJ / BK;   // 8

    load_stage(sb, Ah, Al, Bh, Bl, DPROJ, tid);
    CP_COMMIT();

    for (int kc = 0; kc < NCHUNK; kc++) {
        if (kc + 1 < NCHUNK) {
            int ko = (kc + 1) * BK;
            load_stage(sb + ((kc + 1) & 1) * STAGE_B,
                       Ah + ko, Al + ko, Bh + ko, Bl + ko, DPROJ, tid);
            CP_COMMIT();
            CP_WAIT_1();
        } else {
            CP_WAIT_0();
        }
        __syncthreads();
        compute64(sb + (kc & 1) * STAGE_B, lane, wm, wn, acc);
        __syncthreads();
    }

    const float scale = __ldg(clf_w);
    const float offs  = __ldg(clf_b);
    float* Ob = out + (size_t)bb * SEQ * SEQ;
    const int i0 = bi * 128, j0 = bj * 128;

    // Upper tile: coalesced float2 stores straight from fragments
#pragma unroll
    for (int mf = 0; mf < 4; mf++) {
        int row = i0 + wm * 64 + mf * 16 + (lane >> 2);
#pragma unroll
        for (int nf = 0; nf < 8; nf++) {
            int col = j0 + wn * 64 + nf * 8 + (lane & 3) * 2;
#pragma unroll
            for (int half = 0; half < 2; half++) {
                float2 v;
                v.x = fmaf(acc[mf][nf][half * 2],     scale, offs);
                v.y = fmaf(acc[mf][nf][half * 2 + 1], scale, offs);
                *reinterpret_cast<float2*>(Ob + (size_t)(row + half * 8) * SEQ + col) = v;
            }
        }
    }

    // Mirror tile via padded-SMEM transpose (pitch 133: conflict-free reads)
    if (bi != bj) {
        float* ts = reinterpret_cast<float*>(smem);   // [128][133]
        __syncthreads();
#pragma unroll
        for (int mf = 0; mf < 4; mf++) {
            int rr = wm * 64 + mf * 16 + (lane >> 2);
#pragma unroll
            for (int nf = 0; nf < 8; nf++) {
                int cc = wn * 64 + nf * 8 + (lane & 3) * 2;
#pragma unroll
                for (int half = 0; half < 2; half++) {
                    int r = rr + half * 8;
                    ts[r * 133 + cc]     = fmaf(acc[mf][nf][half * 2],     scale, offs);
                    ts[r * 133 + cc + 1] = fmaf(acc[mf][nf][half * 2 + 1], scale, offs);
                }
            }
        }
        __syncthreads();
#pragma unroll
        for (int q = 0; q < 128; q++) {
            int linear = q * 128 + tid;
            int jj = linear >> 7;
            int ii = linear & 127;
            Ob[(size_t)(j0 + jj) * SEQ + i0 + ii] = ts[ii * 133 + jj];
        }
    }
}

// ---------------------------------------------------------------------------
// Launch
// ---------------------------------------------------------------------------
extern "C" void kernel_launch(void* const* d_in, const int* in_sizes, int n_in,
                              void* d_out, int out_size)
{
    const float* hs = (const float*)d_in[0];
    const float* pw = (const float*)d_in[1];
    const float* pb = (const float*)d_in[2];
    const float* cw = (const float*)d_in[3];
    const float* cb = (const float*)d_in[4];
    float* out = (float*)d_out;

    cudaFuncSetAttribute(proj_mma_kernel,  cudaFuncAttributeMaxDynamicSharedMemorySize, SMEM_SZ);
    cudaFuncSetAttribute(score_mma_kernel, cudaFuncAttributeMaxDynamicSharedMemorySize, SMEM_SZ);

    __nv_bfloat16 *hs_hi, *hs_lo, *pw_hi, *pw_lo;
    cudaGetSymbolAddress((void**)&hs_hi, g_hs_hi);
    cudaGetSymbolAddress((void**)&hs_lo, g_hs_lo);
    cudaGetSymbolAddress((void**)&pw_hi, g_pw_hi);
    cudaGetSymbolAddress((void**)&pw_lo, g_pw_lo);

    int n4_hs = BATCH * SEQ * DMODEL / 4;
    int n4_pw = DPROJ * DMODEL / 4;
    split_kernel<<<(n4_hs + 255) / 256, 256>>>(hs, hs_hi, hs_lo, n4_hs);
    split_kernel<<<(n4_pw + 255) / 256, 256>>>(pw, pw_hi, pw_lo, n4_pw);

    dim3 grid1(BATCH * SEQ / 128, DPROJ / 128);   // (64, 2)
    proj_mma_kernel<<<grid1, 128, SMEM_SZ>>>(pb);

    dim3 grid2(136, BATCH);
    score_mma_kernel<<<grid2, 128, SMEM_SZ>>>(cw, cb, out);
}